// round 13
// baseline (speedup 1.0000x reference)
#include <cuda_runtime.h>
#include <math.h>

// MaskAlignmentLoss: fused kernel, 512-thread blocks.
// Pixel blocks (32): 32x16 tile, single-pass cap-6 binning, exact ring search
//   (RB=4) + overflow list + brute-force guard.
// Vert blocks (108): 256 verts each, 2 threads/vert (up/down row halves),
//   mask bitset via ballot + exact per-row scan.
// B=4, N=6890, H=W=64. Pixel units; scale 1/64 per term.

#define BATCH   4
#define NV      6890
#define HW      4096
#define INF2    1.0e18f
#define INV64   0.015625f
#define BIGF    1.0e9f
#define NT      512
#define NB_PIX  32                  // 8 tiles x 4 batches (32x16 tiles)
#define NB_VERT 108                 // 108*256 = 27648 >= 27560
#define NBLK    (NB_PIX + NB_VERT)  // 140
#define RB      4
#define REGX    40                  // 32 + 2*RB
#define REGY    24                  // 16 + 2*RB
#define NBIN    (REGX * REGY)       // 960
#define CAP     6
#define OVF_CAP 128
#define SMEM_BYTES (NBIN * 4 + NBIN * CAP * 8 + OVF_CAP * 8)   // 50944

// -------- persistent device state (monotonic; no init across replays) --------
__device__ float    g_partial[NBLK];
__device__ unsigned g_ticket;

__device__ __forceinline__ float sqrt_ap(float x) {
    float r; asm("sqrt.approx.f32 %0, %1;" : "=f"(r) : "f"(x)); return r;
}

extern __shared__ __align__(16) unsigned dyn_u[];

__global__ void __launch_bounds__(NT) k_fused(const float* __restrict__ vert,
                                              const int*   __restrict__ mask,
                                              float*       __restrict__ out) {
    __shared__ float red[16];
    __shared__ unsigned s_ovf_cnt;
    __shared__ int s_fallback;
    __shared__ int lastflag;

    const int bx = blockIdx.x, tid = threadIdx.x;
    const int lane = tid & 31, wid = tid >> 5;
    float s = 0.0f;

    if (bx < NB_PIX) {
        // ============ pixel -> nearest vert, one 32x16 tile per block ============
        const int b  = bx >> 3;
        const int t  = bx & 7;
        const int ox = (t & 1) * 32, oy = (t >> 1) * 16;
        const int rx0 = ox - RB, ry0 = oy - RB;
        const int cx = ox + (tid & 31), cy = oy + (tid >> 5);

        unsigned* scnt = dyn_u;                                    // [NBIN]
        float2*   sbin = (float2*)(dyn_u + NBIN);                  // [NBIN*CAP]
        float2*   sovf = (float2*)(dyn_u + NBIN + NBIN * CAP * 2); // [OVF_CAP]

        const int mymask = mask[b * HW + cy * 64 + cx];   // early independent load

        scnt[tid] = 0;
        if (tid < NBIN - NT) scnt[tid + NT] = 0;
        if (tid == 0) { s_ovf_cnt = 0; s_fallback = 0; }
        __syncthreads();

        // single-pass binning, prefetch-pipelined float4 loads (2 verts each).
        // ceil(3445/512) = 7 iterations.
        const float2* vb  = (const float2*)(vert + (size_t)b * NV * 2);
        const float4* vb4 = (const float4*)vb;
        {
            const int half = NV / 2;                      // 3445
            bool vnext = (tid < half);
            float4 qnext = vnext ? vb4[tid] : make_float4(0, 0, 0, 0);
            for (int k = 0; k * NT < half; k++) {
                float4 q = qnext; bool v = vnext;
                int inx = tid + (k + 1) * NT;
                vnext = (inx < half);
                if (vnext) qnext = vb4[inx];
                if (v) {
#pragma unroll
                    for (int h = 0; h < 2; h++) {
                        float vx = h ? q.z : q.x, vy = h ? q.w : q.y;
                        int lx = min(63, (int)vx) - rx0;
                        int ly = min(63, (int)vy) - ry0;
                        if ((unsigned)lx < REGX && (unsigned)ly < REGY) {
                            int bin = ly * REGX + lx;
                            unsigned slot = atomicAdd(&scnt[bin], 1u);
                            if (slot < CAP) {
                                sbin[bin * CAP + slot] = make_float2(vx, vy);
                            } else {
                                unsigned o = atomicAdd(&s_ovf_cnt, 1u);
                                if (o < OVF_CAP) sovf[o] = make_float2(vx, vy);
                                else s_fallback = 1;
                            }
                        }
                    }
                }
            }
        }
        __syncthreads();

        if (mymask > 0) {
            const float px = (float)cx, py = (float)cy;
            float best = INF2;
#define EVAL_VBIN(X, Y) do {                                               \
            int bin = ((Y) - ry0) * REGX + ((X) - rx0);                    \
            int n = min(scnt[bin], (unsigned)CAP);                         \
            for (int k = 0; k < n; k++) {                                  \
                float2 w = sbin[bin * CAP + k];                            \
                float dx = px - w.x, dy = py - w.y;                        \
                best = fminf(best, fmaf(dx, dx, dy * dy));                 \
            } } while (0)
            for (int r = 0; r <= RB; r++) {
                if (r > 0 && best <= (float)((r - 1) * (r - 1))) break;
                int x0 = max(cx - r, 0), x1 = min(cx + r, 63);
                int yt = cy - r;
                if (yt >= 0) for (int x = x0; x <= x1; x++) EVAL_VBIN(x, yt);
                if (r > 0) {
                    int yb = cy + r;
                    if (yb <= 63) for (int x = x0; x <= x1; x++) EVAL_VBIN(x, yb);
                    int yy0 = max(cy - r + 1, 0), yy1 = min(cy + r - 1, 63);
                    int xl = cx - r, xr = cx + r;
                    if (xl >= 0)  for (int y = yy0; y <= yy1; y++) EVAL_VBIN(xl, y);
                    if (xr <= 63) for (int y = yy0; y <= yy1; y++) EVAL_VBIN(xr, y);
                }
            }
            // unconditional overflow scan (real verts -> cannot underestimate)
            int no = min(s_ovf_cnt, (unsigned)OVF_CAP);
            for (int k = 0; k < no; k++) {
                float2 w = sovf[k];
                float dx = px - w.x, dy = py - w.y;
                best = fminf(best, fmaf(dx, dx, dy * dy));
            }
            // exactness guards: region miss (best > RB^2) or list overflow
            if (s_fallback || !(best <= (float)(RB * RB))) {
                for (int i = 0; i < NV; i++) {
                    float2 w = vb[i];
                    float dx = px - w.x, dy = py - w.y;
                    best = fminf(best, fmaf(dx, dx, dy * dy));
                }
            }
            s = sqrt_ap(best) * INV64;
        }
    } else {
        // ====== vert -> nearest valid pixel: 256 verts/block, 2 threads/vert ======
        const int g0 = (bx - NB_PIX) * 256;
        const int b_lo = g0 / NV;
        const int b_hi = min((g0 + 255) / NV, BATCH - 1);
        unsigned* sb = dyn_u;    // up to 2*128 bitset words

        for (int bi = 0; bi <= b_hi - b_lo; bi++) {
            const int* mbase = mask + (b_lo + bi) * HW;
            // 128 words over 16 warps: 8 ballots per warp
#pragma unroll
            for (int it = 0; it < 8; it++) {
                int wl = it * 16 + wid;
                int val = mbase[wl * 32 + lane] > 0;
                unsigned word = __ballot_sync(0xffffffffu, val);
                if (lane == 0) sb[bi * 128 + wl] = word;
            }
        }
        __syncthreads();

        const int g = g0 + (tid >> 1);          // vert index
        const int half = tid & 1;               // 0: rows y<=cy, 1: rows y>cy
        float best = INF2;
        bool act = (g < BATCH * NV);
        if (act) {
            const int b = g / NV;
            float2 v = ((const float2*)vert)[g];
            const float vx = v.x, vy = v.y;
            const int xc = min(63, (int)vx), cy = min(63, (int)vy);
            const unsigned* mb = &sb[(b - b_lo) * 128];
            const unsigned long long lmask =
                (xc >= 63) ? ~0ull : ((1ull << (xc + 1)) - 1ull);

            // exact per-row minimum via two monotone candidate sets:
            //  highest set bit <= xc, lowest set bit >= xc+1
#define ROW_EVAL(Y, DY) do {                                                     \
            unsigned long long m = (unsigned long long)mb[2 * (Y)] |             \
                                   ((unsigned long long)mb[2 * (Y) + 1] << 32);  \
            if (m) {                                                             \
                float dy2 = (DY) * (DY);                                         \
                unsigned long long ml = m & lmask;                               \
                if (ml) {                                                        \
                    float dx = vx - (float)(63 - __clzll((long long)ml));        \
                    best = fminf(best, fmaf(dx, dx, dy2));                       \
                }                                                                \
                unsigned long long mr = (m >> xc) >> 1;                          \
                if (mr) {                                                        \
                    float dx = (float)(xc + __ffsll((long long)mr)) - vx;        \
                    best = fminf(best, fmaf(dx, dx, dy2));                       \
                }                                                                \
            } } while (0)

            if (half == 0) {
                // rows cy, cy-1, ... , 0
                for (int d = 0; d <= cy; d++) {
                    if (d > 0 && best <= (float)((d - 1) * (d - 1))) break;
                    int y = cy - d;
                    float dy = vy - (float)y;
                    if (dy * dy < best) ROW_EVAL(y, dy);
                }
            } else {
                // rows cy+1, ... , 63
                for (int d = 1; cy + d < 64; d++) {
                    if (best <= (float)((d - 1) * (d - 1))) break;
                    int y = cy + d;
                    float dy = (float)y - vy;
                    if (dy * dy < best) ROW_EVAL(y, dy);
                }
            }
        }
        // combine the two halves of each vert
        float other = __shfl_xor_sync(0xffffffffu, best, 1);
        best = fminf(best, other);
        if (act && half == 0)
            s = (best >= 1.0e17f) ? BIGF : sqrt_ap(best) * INV64;
    }

    // ===== block reduce (shuffle) -> partial; last finisher sums all =====
    {
        float v = s;
#pragma unroll
        for (int o = 16; o > 0; o >>= 1) v += __shfl_down_sync(0xffffffffu, v, o);
        if (lane == 0) red[wid] = v;
    }
    __syncthreads();
    if (tid == 0) {
        float v = 0.f;
#pragma unroll
        for (int w = 0; w < 16; w++) v += red[w];
        g_partial[bx] = v;
        __threadfence();
        unsigned t = atomicAdd(&g_ticket, 1u);
        lastflag = ((t % (unsigned)NBLK) == (unsigned)(NBLK - 1));
    }
    __syncthreads();
    if (lastflag) {
        __threadfence();
        float v = (tid < NBLK) ? *(volatile float*)&g_partial[tid] : 0.0f;
#pragma unroll
        for (int o = 16; o > 0; o >>= 1) v += __shfl_down_sync(0xffffffffu, v, o);
        if (lane == 0) red[wid] = v;
        __syncthreads();
        if (tid == 0) {
            float r = 0.f;
#pragma unroll
            for (int w = 0; w < 16; w++) r += red[w];
            out[0] = r;
        }
    }
}

extern "C" void kernel_launch(void* const* d_in, const int* in_sizes, int n_in,
                              void* d_out, int out_size) {
    const float* vert2d = (const float*)d_in[0];   // [B, N, 2] float32 (pixel units)
    const int*   mask   = (const int*)d_in[1];     // [B, H, W] int32
    float* out = (float*)d_out;
    (void)in_sizes; (void)n_in; (void)out_size;

    static int configured = 0;
    if (!configured) {
        cudaFuncSetAttribute(k_fused, cudaFuncAttributeMaxDynamicSharedMemorySize, SMEM_BYTES);
        configured = 1;
    }
    k_fused<<<NBLK, NT, SMEM_BYTES>>>(vert2d, mask, out);
}

// round 14
// speedup vs baseline: 1.0374x; 1.0374x over previous
#include <cuda_runtime.h>
#include <math.h>

// MaskAlignmentLoss: fused kernel, branchless common-path searches.
// Pixel blocks (32): 32x16 tile, single-pass cap-6 binning; unrolled 3x3 bin
//   stage (exact if best<=1), 5x5 outer ring (exact if best<=4), brute guard.
// Vert blocks (108): 2 threads/vert; fixed +-4-row unrolled bitset scan
//   (exact if best<=16), full-scan fallback.
// B=4, N=6890, H=W=64. Pixel units; scale 1/64 per term.

#define BATCH   4
#define NV      6890
#define HW      4096
#define INF2    1.0e18f
#define INV64   0.015625f
#define BIGF    1.0e9f
#define NT      512
#define NB_PIX  32                  // 8 tiles x 4 batches (32x16 tiles)
#define NB_VERT 108                 // 108*256 = 27648 >= 27560
#define NBLK    (NB_PIX + NB_VERT)  // 140
#define RB      4
#define REGX    40                  // 32 + 2*RB
#define REGY    24                  // 16 + 2*RB
#define NBIN    (REGX * REGY)       // 960
#define CAP     6
#define OVF_CAP 128
#define SMEM_BYTES (NBIN * 4 + NBIN * CAP * 8 + OVF_CAP * 8)   // 50944

// -------- persistent device state (monotonic; no init across replays) --------
__device__ float    g_partial[NBLK];
__device__ unsigned g_ticket;

__device__ __forceinline__ float sqrt_ap(float x) {
    float r; asm("sqrt.approx.f32 %0, %1;" : "=f"(r) : "f"(x)); return r;
}

extern __shared__ __align__(16) unsigned dyn_u[];

__global__ void __launch_bounds__(NT) k_fused(const float* __restrict__ vert,
                                              const int*   __restrict__ mask,
                                              float*       __restrict__ out) {
    __shared__ float red[16];
    __shared__ unsigned s_ovf_cnt;
    __shared__ int s_fallback;
    __shared__ int lastflag;

    const int bx = blockIdx.x, tid = threadIdx.x;
    const int lane = tid & 31, wid = tid >> 5;
    float s = 0.0f;

    if (bx < NB_PIX) {
        // ============ pixel -> nearest vert, one 32x16 tile per block ============
        const int b  = bx >> 3;
        const int t  = bx & 7;
        const int ox = (t & 1) * 32, oy = (t >> 1) * 16;
        const int rx0 = ox - RB, ry0 = oy - RB;
        const int cx = ox + (tid & 31), cy = oy + (tid >> 5);

        unsigned* scnt = dyn_u;                                    // [NBIN]
        float2*   sbin = (float2*)(dyn_u + NBIN);                  // [NBIN*CAP]
        float2*   sovf = (float2*)(dyn_u + NBIN + NBIN * CAP * 2); // [OVF_CAP]

        const int mymask = mask[b * HW + cy * 64 + cx];   // early independent load

        scnt[tid] = 0;
        if (tid < NBIN - NT) scnt[tid + NT] = 0;
        if (tid == 0) { s_ovf_cnt = 0; s_fallback = 0; }
        __syncthreads();

        // single-pass binning, prefetch-pipelined float4 loads (2 verts each).
        const float2* vb  = (const float2*)(vert + (size_t)b * NV * 2);
        const float4* vb4 = (const float4*)vb;
        {
            const int half = NV / 2;                      // 3445
            bool vnext = (tid < half);
            float4 qnext = vnext ? vb4[tid] : make_float4(0, 0, 0, 0);
            for (int k = 0; k * NT < half; k++) {
                float4 q = qnext; bool v = vnext;
                int inx = tid + (k + 1) * NT;
                vnext = (inx < half);
                if (vnext) qnext = vb4[inx];
                if (v) {
#pragma unroll
                    for (int h = 0; h < 2; h++) {
                        float vx = h ? q.z : q.x, vy = h ? q.w : q.y;
                        int lx = min(63, (int)vx) - rx0;
                        int ly = min(63, (int)vy) - ry0;
                        if ((unsigned)lx < REGX && (unsigned)ly < REGY) {
                            int bin = ly * REGX + lx;
                            unsigned slot = atomicAdd(&scnt[bin], 1u);
                            if (slot < CAP) {
                                sbin[bin * CAP + slot] = make_float2(vx, vy);
                            } else {
                                unsigned o = atomicAdd(&s_ovf_cnt, 1u);
                                if (o < OVF_CAP) sovf[o] = make_float2(vx, vy);
                                else s_fallback = 1;
                            }
                        }
                    }
                }
            }
        }
        __syncthreads();

        if (mymask > 0) {
            const float px = (float)cx, py = (float)cy;
            float best = INF2;
            // region coords of the 5x5 window are always in-array (RB=4 >= 2);
            // out-of-image cells are simply empty bins.
            const int base = (cy - ry0) * REGX + (cx - rx0);
#define EVAL_VBIN_OFS(OFS) do {                                            \
            int bin = base + (OFS);                                        \
            int n = min(scnt[bin], (unsigned)CAP);                         \
            for (int k = 0; k < n; k++) {                                  \
                float2 w = sbin[bin * CAP + k];                            \
                float dx = px - w.x, dy = py - w.y;                        \
                best = fminf(best, fmaf(dx, dx, dy * dy));                 \
            } } while (0)

            if (s_fallback) {
                for (int i = 0; i < NV; i++) {
                    float2 w = vb[i];
                    float dx = px - w.x, dy = py - w.y;
                    best = fminf(best, fmaf(dx, dx, dy * dy));
                }
            } else {
                // stage 1: 3x3 bins, fully unrolled (counts batch as 9 LDS)
#pragma unroll
                for (int dyy = -1; dyy <= 1; dyy++)
#pragma unroll
                    for (int dxx = -1; dxx <= 1; dxx++)
                        EVAL_VBIN_OFS(dyy * REGX + dxx);
                // overflow list (real verts; cannot underestimate)
                int no = min(s_ovf_cnt, (unsigned)OVF_CAP);
                for (int k = 0; k < no; k++) {
                    float2 w = sovf[k];
                    float dx = px - w.x, dy = py - w.y;
                    best = fminf(best, fmaf(dx, dx, dy * dy));
                }
                // outside the 3x3 cells every vert has d > 1
                if (!(best <= 1.0f)) {
                    // stage 2: Chebyshev ring 2 (16 bins), unrolled
#pragma unroll
                    for (int dxx = -2; dxx <= 2; dxx++) {
                        EVAL_VBIN_OFS(-2 * REGX + dxx);
                        EVAL_VBIN_OFS( 2 * REGX + dxx);
                    }
#pragma unroll
                    for (int dyy = -1; dyy <= 1; dyy++) {
                        EVAL_VBIN_OFS(dyy * REGX - 2);
                        EVAL_VBIN_OFS(dyy * REGX + 2);
                    }
                    // outside the 5x5 cells every vert has d > 2
                    if (!(best <= 4.0f)) {
                        for (int i = 0; i < NV; i++) {
                            float2 w = vb[i];
                            float dx = px - w.x, dy = py - w.y;
                            best = fminf(best, fmaf(dx, dx, dy * dy));
                        }
                    }
                }
            }
            s = sqrt_ap(best) * INV64;
        }
    } else {
        // ====== vert -> nearest valid pixel: 256 verts/block, 2 threads/vert ======
        const int g0 = (bx - NB_PIX) * 256;
        const int b_lo = g0 / NV;
        const int b_hi = min((g0 + 255) / NV, BATCH - 1);
        unsigned* sb = dyn_u;    // up to 2*128 bitset words

        for (int bi = 0; bi <= b_hi - b_lo; bi++) {
            const int* mbase = mask + (b_lo + bi) * HW;
#pragma unroll
            for (int it = 0; it < 8; it++) {
                int wl = it * 16 + wid;
                int val = mbase[wl * 32 + lane] > 0;
                unsigned word = __ballot_sync(0xffffffffu, val);
                if (lane == 0) sb[bi * 128 + wl] = word;
            }
        }
        __syncthreads();

        const int g = g0 + (tid >> 1);          // vert index
        const int half = tid & 1;               // 0: dy 0..-4, 1: dy +1..+4
        float best = INF2;
        bool act = (g < BATCH * NV);
        float vx = 0.f, vy = 0.f;
        int xc = 0, cy = 0;
        const unsigned* mb = sb;
        if (act) {
            const int b = g / NV;
            float2 v = ((const float2*)vert)[g];
            vx = v.x; vy = v.y;
            xc = min(63, (int)vx); cy = min(63, (int)vy);
            mb = &sb[(b - b_lo) * 128];
        }
        const unsigned long long lmask =
            (xc >= 63) ? ~0ull : ((1ull << (xc + 1)) - 1ull);

        // exact per-row minimum via two monotone candidate sets:
        //  highest set bit <= xc, lowest set bit >= xc+1
#define ROW_EVAL(Y, DY) do {                                                     \
        unsigned long long m = (unsigned long long)mb[2 * (Y)] |                 \
                               ((unsigned long long)mb[2 * (Y) + 1] << 32);      \
        if (m) {                                                                 \
            float dy2 = (DY) * (DY);                                             \
            unsigned long long ml = m & lmask;                                   \
            if (ml) {                                                            \
                float dx = vx - (float)(63 - __clzll((long long)ml));            \
                best = fminf(best, fmaf(dx, dx, dy2));                           \
            }                                                                    \
            unsigned long long mr = (m >> xc) >> 1;                              \
            if (mr) {                                                            \
                float dx = (float)(xc + __ffsll((long long)mr)) - vx;            \
                best = fminf(best, fmaf(dx, dx, dy2));                           \
            }                                                                    \
        } } while (0)

        if (act) {
            if (half == 0) {
                // rows cy, cy-1, ..., cy-4 (unrolled; predicated bounds)
#pragma unroll
                for (int d = 0; d <= 4; d++) {
                    int y = cy - d;
                    if (y >= 0) { float dy = vy - (float)y; ROW_EVAL(y, dy); }
                }
            } else {
                // rows cy+1 .. cy+4
#pragma unroll
                for (int d = 1; d <= 4; d++) {
                    int y = cy + d;
                    if (y < 64) { float dy = (float)y - vy; ROW_EVAL(y, dy); }
                }
            }
        }
        // combine halves; rows beyond +-4 have d^2 > 16
        float other = __shfl_xor_sync(0xffffffffu, best, 1);
        best = fminf(best, other);
        if (act && half == 0) {
            if (!(best <= 16.0f)) {          // rare exact fallback (covers empty mask)
                best = INF2;
                for (int y = 0; y < 64; y++) {
                    float dy = vy - (float)y;
                    if (dy * dy < best) ROW_EVAL(y, dy);
                }
            }
            s = (best >= 1.0e17f) ? BIGF : sqrt_ap(best) * INV64;
        }
    }

    // ===== block reduce (shuffle) -> partial; last finisher sums all =====
    {
        float v = s;
#pragma unroll
        for (int o = 16; o > 0; o >>= 1) v += __shfl_down_sync(0xffffffffu, v, o);
        if (lane == 0) red[wid] = v;
    }
    __syncthreads();
    if (tid == 0) {
        float v = 0.f;
#pragma unroll
        for (int w = 0; w < 16; w++) v += red[w];
        g_partial[bx] = v;
        __threadfence();
        unsigned t = atomicAdd(&g_ticket, 1u);
        lastflag = ((t % (unsigned)NBLK) == (unsigned)(NBLK - 1));
    }
    __syncthreads();
    if (lastflag) {
        __threadfence();
        float v = (tid < NBLK) ? *(volatile float*)&g_partial[tid] : 0.0f;
#pragma unroll
        for (int o = 16; o > 0; o >>= 1) v += __shfl_down_sync(0xffffffffu, v, o);
        if (lane == 0) red[wid] = v;
        __syncthreads();
        if (tid == 0) {
            float r = 0.f;
#pragma unroll
            for (int w = 0; w < 16; w++) r += red[w];
            out[0] = r;
        }
    }
}

extern "C" void kernel_launch(void* const* d_in, const int* in_sizes, int n_in,
                              void* d_out, int out_size) {
    const float* vert2d = (const float*)d_in[0];   // [B, N, 2] float32 (pixel units)
    const int*   mask   = (const int*)d_in[1];     // [B, H, W] int32
    float* out = (float*)d_out;
    (void)in_sizes; (void)n_in; (void)out_size;

    static int configured = 0;
    if (!configured) {
        cudaFuncSetAttribute(k_fused, cudaFuncAttributeMaxDynamicSharedMemorySize, SMEM_BYTES);
        configured = 1;
    }
    k_fused<<<NBLK, NT, SMEM_BYTES>>>(vert2d, mask, out);
}

// round 15
// speedup vs baseline: 1.0466x; 1.0089x over previous
#include <cuda_runtime.h>
#include <math.h>

// MaskAlignmentLoss: fused kernel, branchless searches + deep-pipelined loads.
// Pixel blocks (32): 32x16 tile, single-pass cap-6 binning (depth-4 prefetch);
//   unrolled 3x3 stage (exact if best<=1), 5x5 ring (exact if best<=4), guard.
// Vert blocks (108): 2 threads/vert; register-batched mask loads + ballot;
//   fixed +-4-row bitset scan (exact if best<=16), full-scan fallback.
// B=4, N=6890, H=W=64. Pixel units; scale 1/64 per term.

#define BATCH   4
#define NV      6890
#define HW      4096
#define INF2    1.0e18f
#define INV64   0.015625f
#define BIGF    1.0e9f
#define NT      512
#define NB_PIX  32                  // 8 tiles x 4 batches (32x16 tiles)
#define NB_VERT 108                 // 108*256 = 27648 >= 27560
#define NBLK    (NB_PIX + NB_VERT)  // 140
#define RB      4
#define REGX    40                  // 32 + 2*RB
#define REGY    24                  // 16 + 2*RB
#define NBIN    (REGX * REGY)       // 960
#define CAP     6
#define OVF_CAP 128
#define SMEM_BYTES (NBIN * 4 + NBIN * CAP * 8 + OVF_CAP * 8)   // 50944

// -------- persistent device state (monotonic; no init across replays) --------
__device__ float    g_partial[NBLK];
__device__ unsigned g_ticket;

__device__ __forceinline__ float sqrt_ap(float x) {
    float r; asm("sqrt.approx.f32 %0, %1;" : "=f"(r) : "f"(x)); return r;
}

extern __shared__ __align__(16) unsigned dyn_u[];

__global__ void __launch_bounds__(NT) k_fused(const float* __restrict__ vert,
                                              const int*   __restrict__ mask,
                                              float*       __restrict__ out) {
    __shared__ float red[16];
    __shared__ unsigned s_ovf_cnt;
    __shared__ int s_fallback;
    __shared__ int lastflag;

    const int bx = blockIdx.x, tid = threadIdx.x;
    const int lane = tid & 31, wid = tid >> 5;
    float s = 0.0f;

    if (bx < NB_PIX) {
        // ============ pixel -> nearest vert, one 32x16 tile per block ============
        const int b  = bx >> 3;
        const int t  = bx & 7;
        const int ox = (t & 1) * 32, oy = (t >> 1) * 16;
        const int rx0 = ox - RB, ry0 = oy - RB;
        const int cx = ox + (tid & 31), cy = oy + (tid >> 5);

        unsigned* scnt = dyn_u;                                    // [NBIN]
        float2*   sbin = (float2*)(dyn_u + NBIN);                  // [NBIN*CAP]
        float2*   sovf = (float2*)(dyn_u + NBIN + NBIN * CAP * 2); // [OVF_CAP]

        const int mymask = mask[b * HW + cy * 64 + cx];   // early independent load

        const float2* vb  = (const float2*)(vert + (size_t)b * NV * 2);
        const float4* vb4 = (const float4*)vb;
        const int half = NV / 2;                           // 3445
        // issue first 4 loads BEFORE the zero loop so they overlap it
        float4 q0, q1, q2, q3;
        {
            int i0 = tid, i1 = tid + NT, i2 = tid + 2 * NT, i3 = tid + 3 * NT;
            q0 = (i0 < half) ? __ldg(&vb4[i0]) : make_float4(0, 0, 0, 0);
            q1 = (i1 < half) ? __ldg(&vb4[i1]) : make_float4(0, 0, 0, 0);
            q2 = (i2 < half) ? __ldg(&vb4[i2]) : make_float4(0, 0, 0, 0);
            q3 = (i3 < half) ? __ldg(&vb4[i3]) : make_float4(0, 0, 0, 0);
        }

        scnt[tid] = 0;
        if (tid < NBIN - NT) scnt[tid + NT] = 0;
        if (tid == 0) { s_ovf_cnt = 0; s_fallback = 0; }
        __syncthreads();

#define BIN_ONE(VX, VY) do {                                               \
        float vx_ = (VX), vy_ = (VY);                                      \
        int lx = min(63, (int)vx_) - rx0;                                  \
        int ly = min(63, (int)vy_) - ry0;                                  \
        if ((unsigned)lx < REGX && (unsigned)ly < REGY) {                  \
            int bin = ly * REGX + lx;                                      \
            unsigned slot = atomicAdd(&scnt[bin], 1u);                     \
            if (slot < CAP) sbin[bin * CAP + slot] = make_float2(vx_, vy_);\
            else {                                                         \
                unsigned o = atomicAdd(&s_ovf_cnt, 1u);                    \
                if (o < OVF_CAP) sovf[o] = make_float2(vx_, vy_);          \
                else s_fallback = 1;                                       \
            }                                                              \
        } } while (0)
#define BIN_Q(Q, IDX) do {                                                 \
        if ((IDX) < half) { BIN_ONE((Q).x, (Q).y); BIN_ONE((Q).z, (Q).w); } } while (0)

        // depth-4 software pipeline: ceil(3445/512)=7 iterations
        for (int k = 0; k * NT < half; k += 4) {
            float4 a0 = q0, a1 = q1, a2 = q2, a3 = q3;
            int n0 = tid + (k + 4) * NT, n1 = n0 + NT, n2 = n1 + NT, n3 = n2 + NT;
            q0 = (n0 < half) ? __ldg(&vb4[n0]) : make_float4(0, 0, 0, 0);
            q1 = (n1 < half) ? __ldg(&vb4[n1]) : make_float4(0, 0, 0, 0);
            q2 = (n2 < half) ? __ldg(&vb4[n2]) : make_float4(0, 0, 0, 0);
            q3 = (n3 < half) ? __ldg(&vb4[n3]) : make_float4(0, 0, 0, 0);
            BIN_Q(a0, tid + k * NT);
            BIN_Q(a1, tid + (k + 1) * NT);
            BIN_Q(a2, tid + (k + 2) * NT);
            BIN_Q(a3, tid + (k + 3) * NT);
        }
        __syncthreads();

        if (mymask > 0) {
            const float px = (float)cx, py = (float)cy;
            float best = INF2;
            const int base = (cy - ry0) * REGX + (cx - rx0);
#define EVAL_VBIN_OFS(OFS) do {                                            \
            int bin = base + (OFS);                                        \
            int n = min(scnt[bin], (unsigned)CAP);                         \
            for (int k = 0; k < n; k++) {                                  \
                float2 w = sbin[bin * CAP + k];                            \
                float dx = px - w.x, dy = py - w.y;                        \
                best = fminf(best, fmaf(dx, dx, dy * dy));                 \
            } } while (0)

            if (s_fallback) {
                for (int i = 0; i < NV; i++) {
                    float2 w = vb[i];
                    float dx = px - w.x, dy = py - w.y;
                    best = fminf(best, fmaf(dx, dx, dy * dy));
                }
            } else {
                // stage 1: 3x3 bins (RB=4 margin keeps window in-array)
#pragma unroll
                for (int dyy = -1; dyy <= 1; dyy++)
#pragma unroll
                    for (int dxx = -1; dxx <= 1; dxx++)
                        EVAL_VBIN_OFS(dyy * REGX + dxx);
                int no = min(s_ovf_cnt, (unsigned)OVF_CAP);
                for (int k = 0; k < no; k++) {
                    float2 w = sovf[k];
                    float dx = px - w.x, dy = py - w.y;
                    best = fminf(best, fmaf(dx, dx, dy * dy));
                }
                if (!(best <= 1.0f)) {            // outside 3x3 => d > 1
#pragma unroll
                    for (int dxx = -2; dxx <= 2; dxx++) {
                        EVAL_VBIN_OFS(-2 * REGX + dxx);
                        EVAL_VBIN_OFS( 2 * REGX + dxx);
                    }
#pragma unroll
                    for (int dyy = -1; dyy <= 1; dyy++) {
                        EVAL_VBIN_OFS(dyy * REGX - 2);
                        EVAL_VBIN_OFS(dyy * REGX + 2);
                    }
                    if (!(best <= 4.0f)) {        // outside 5x5 => d > 2
                        for (int i = 0; i < NV; i++) {
                            float2 w = vb[i];
                            float dx = px - w.x, dy = py - w.y;
                            best = fminf(best, fmaf(dx, dx, dy * dy));
                        }
                    }
                }
            }
            s = sqrt_ap(best) * INV64;
        }
    } else {
        // ====== vert -> nearest valid pixel: 256 verts/block, 2 threads/vert ======
        const int g0 = (bx - NB_PIX) * 256;
        const int b_lo = g0 / NV;
        const int b_hi = min((g0 + 255) / NV, BATCH - 1);
        unsigned* sb = dyn_u;    // up to 2*128 bitset words

        for (int bi = 0; bi <= b_hi - b_lo; bi++) {
            const int* mbase = mask + (b_lo + bi) * HW;
            // batch all 8 loads into registers, then ballot from registers
            int mv[8];
#pragma unroll
            for (int it = 0; it < 8; it++)
                mv[it] = __ldg(&mbase[(it * 16 + wid) * 32 + lane]);
#pragma unroll
            for (int it = 0; it < 8; it++) {
                unsigned word = __ballot_sync(0xffffffffu, mv[it] > 0);
                if (lane == 0) sb[bi * 128 + it * 16 + wid] = word;
            }
        }
        __syncthreads();

        const int g = g0 + (tid >> 1);          // vert index
        const int half = tid & 1;               // 0: dy 0..-4, 1: dy +1..+4
        float best = INF2;
        bool act = (g < BATCH * NV);
        float vx = 0.f, vy = 0.f;
        int xc = 0, cy = 0;
        const unsigned* mb = sb;
        if (act) {
            const int b = g / NV;
            float2 v = ((const float2*)vert)[g];
            vx = v.x; vy = v.y;
            xc = min(63, (int)vx); cy = min(63, (int)vy);
            mb = &sb[(b - b_lo) * 128];
        }
        const unsigned long long lmask =
            (xc >= 63) ? ~0ull : ((1ull << (xc + 1)) - 1ull);

        // exact per-row minimum via two monotone candidate sets:
        //  highest set bit <= xc, lowest set bit >= xc+1
#define ROW_EVAL(Y, DY) do {                                                     \
        unsigned long long m = (unsigned long long)mb[2 * (Y)] |                 \
                               ((unsigned long long)mb[2 * (Y) + 1] << 32);      \
        if (m) {                                                                 \
            float dy2 = (DY) * (DY);                                             \
            unsigned long long ml = m & lmask;                                   \
            if (ml) {                                                            \
                float dx = vx - (float)(63 - __clzll((long long)ml));            \
                best = fminf(best, fmaf(dx, dx, dy2));                           \
            }                                                                    \
            unsigned long long mr = (m >> xc) >> 1;                              \
            if (mr) {                                                            \
                float dx = (float)(xc + __ffsll((long long)mr)) - vx;            \
                best = fminf(best, fmaf(dx, dx, dy2));                           \
            }                                                                    \
        } } while (0)

        if (act) {
            if (half == 0) {
#pragma unroll
                for (int d = 0; d <= 4; d++) {
                    int y = cy - d;
                    if (y >= 0) { float dy = vy - (float)y; ROW_EVAL(y, dy); }
                }
            } else {
#pragma unroll
                for (int d = 1; d <= 4; d++) {
                    int y = cy + d;
                    if (y < 64) { float dy = (float)y - vy; ROW_EVAL(y, dy); }
                }
            }
        }
        float other = __shfl_xor_sync(0xffffffffu, best, 1);
        best = fminf(best, other);
        if (act && half == 0) {
            if (!(best <= 16.0f)) {          // rare exact fallback (covers empty mask)
                best = INF2;
                for (int y = 0; y < 64; y++) {
                    float dy = vy - (float)y;
                    if (dy * dy < best) ROW_EVAL(y, dy);
                }
            }
            s = (best >= 1.0e17f) ? BIGF : sqrt_ap(best) * INV64;
        }
    }

    // ===== block reduce (shuffle) -> partial; last finisher sums all =====
    {
        float v = s;
#pragma unroll
        for (int o = 16; o > 0; o >>= 1) v += __shfl_down_sync(0xffffffffu, v, o);
        if (lane == 0) red[wid] = v;
    }
    __syncthreads();
    if (tid == 0) {
        float v = 0.f;
#pragma unroll
        for (int w = 0; w < 16; w++) v += red[w];
        g_partial[bx] = v;
        __threadfence();
        unsigned t = atomicAdd(&g_ticket, 1u);
        lastflag = ((t % (unsigned)NBLK) == (unsigned)(NBLK - 1));
    }
    __syncthreads();
    if (lastflag) {
        __threadfence();
        float v = (tid < NBLK) ? *(volatile float*)&g_partial[tid] : 0.0f;
#pragma unroll
        for (int o = 16; o > 0; o >>= 1) v += __shfl_down_sync(0xffffffffu, v, o);
        if (lane == 0) red[wid] = v;
        __syncthreads();
        if (tid == 0) {
            float r = 0.f;
#pragma unroll
            for (int w = 0; w < 16; w++) r += red[w];
            out[0] = r;
        }
    }
}

extern "C" void kernel_launch(void* const* d_in, const int* in_sizes, int n_in,
                              void* d_out, int out_size) {
    const float* vert2d = (const float*)d_in[0];   // [B, N, 2] float32 (pixel units)
    const int*   mask   = (const int*)d_in[1];     // [B, H, W] int32
    float* out = (float*)d_out;
    (void)in_sizes; (void)n_in; (void)out_size;

    static int configured = 0;
    if (!configured) {
        cudaFuncSetAttribute(k_fused, cudaFuncAttributeMaxDynamicSharedMemorySize, SMEM_BYTES);
        configured = 1;
    }
    k_fused<<<NBLK, NT, SMEM_BYTES>>>(vert2d, mask, out);
}